// round 8
// baseline (speedup 1.0000x reference)
#include <cuda_runtime.h>
#include <cuda_bf16.h>
#include <stdint.h>

#define NWIN   512
#define T_     64
#define C_     512
#define NH_    8
#define D_     64
#define MROWS  32768        // NWIN * T_
#define N_QKV  1536
#define SCALE_ 0.125f

// ---------------- scratch ----------------
__device__ __nv_bfloat16 g_xw [MROWS * C_];      // gathered+rolled x, bf16
__device__ __nv_bfloat16 g_qkv[MROWS * N_QKV];   // Q|K|V concat
__device__ __nv_bfloat16 g_o  [MROWS * C_];      // attention out
__device__ __nv_bfloat16 g_wT [N_QKV * C_];      // [out col][k]
__device__ __nv_bfloat16 g_woT[C_ * C_];         // [out c][k=hd]

// ---------------- asm helpers ----------------
__device__ __forceinline__ void mma16816(float* c, uint32_t a0, uint32_t a1, uint32_t a2, uint32_t a3,
                                         uint32_t b0, uint32_t b1) {
    asm volatile(
        "mma.sync.aligned.m16n8k16.row.col.f32.bf16.bf16.f32 "
        "{%0,%1,%2,%3}, {%4,%5,%6,%7}, {%8,%9}, {%0,%1,%2,%3};"
        : "+f"(c[0]), "+f"(c[1]), "+f"(c[2]), "+f"(c[3])
        : "r"(a0), "r"(a1), "r"(a2), "r"(a3), "r"(b0), "r"(b1));
}
__device__ __forceinline__ void ldsm4(uint32_t* r, uint32_t addr) {
    asm volatile("ldmatrix.sync.aligned.m8n8.x4.shared.b16 {%0,%1,%2,%3}, [%4];"
                 : "=r"(r[0]), "=r"(r[1]), "=r"(r[2]), "=r"(r[3]) : "r"(addr));
}
__device__ __forceinline__ void ldsm4t(uint32_t* r, uint32_t addr) {
    asm volatile("ldmatrix.sync.aligned.m8n8.x4.trans.shared.b16 {%0,%1,%2,%3}, [%4];"
                 : "=r"(r[0]), "=r"(r[1]), "=r"(r[2]), "=r"(r[3]) : "r"(addr));
}
__device__ __forceinline__ void cp16(uint32_t smem_dst, const void* gmem_src) {
    asm volatile("cp.async.cg.shared.global [%0], [%1], 16;" :: "r"(smem_dst), "l"(gmem_src));
}
__device__ __forceinline__ void cp_commit() { asm volatile("cp.async.commit_group;"); }
template<int N> __device__ __forceinline__ void cp_wait() { asm volatile("cp.async.wait_group %0;" :: "n"(N)); }
__device__ __forceinline__ uint32_t smem_u32(const void* p) {
    return (uint32_t)__cvta_generic_to_shared(p);
}
__device__ __forceinline__ uint32_t pack_bf16(float a, float b) {
    __nv_bfloat162 t = __floats2bfloat162_rn(a, b);
    return *reinterpret_cast<uint32_t*>(&t);
}

// ---------------- K0: fused weight-convert + input-gather ----------------
// blocks [0,1024): weight convert/transpose.  blocks [1024,17408): x gather.
__global__ __launch_bounds__(256) void prep_kernel(const float* __restrict__ x,
                                                   const float* __restrict__ wq,
                                                   const float* __restrict__ wk,
                                                   const float* __restrict__ wv,
                                                   const float* __restrict__ wo) {
    if (blockIdx.x < 1024) {
        int idx = blockIdx.x * 256 + threadIdx.x;     // 0..262143
        int r = idx >> 9;
        int j = idx & 511;
        g_wT[j * C_ + r]          = __float2bfloat16(wq[idx]);
        g_wT[(512 + j) * C_ + r]  = __float2bfloat16(wk[idx]);
        g_wT[(1024 + j) * C_ + r] = __float2bfloat16(wv[idx]);
        g_woT[j * C_ + r]         = __float2bfloat16(wo[idx]);
    } else {
        int idx = (blockIdx.x - 1024) * 256 + threadIdx.x;  // 0..4194303
        int row = idx >> 7;
        int ch  = idx & 127;
        int win = row >> 6, t = row & 63;
        int b = win >> 6, wh = (win >> 3) & 7, ww = win & 7;
        int i = t >> 3, j = t & 7;
        int r  = (wh * 8 + i + 4) & 63;
        int cc = (ww * 8 + j + 4) & 63;
        float4 f = *reinterpret_cast<const float4*>(x + (((b * 64 + r) * 64 + cc) << 9) + ch * 4);
        uint2 o;
        o.x = pack_bf16(f.x, f.y);
        o.y = pack_bf16(f.z, f.w);
        *reinterpret_cast<uint2*>(g_xw + row * C_ + ch * 4) = o;
    }
}

// ---------------- GEMM config: BM=128, BN=128, BK=32, S=5 stages, 128 threads ----------------
// 4 warps in 2x2 arrangement -> warp tile 64x64, acc 128 regs/thread
#define BK_         32
#define TSTR_       40                      // bf16 elems per smem row (80B, ldsm conflict-free)
#define ROW_B       (TSTR_ * 2)             // 80 bytes per row
#define STAGE_ROWS  256                     // 128 A rows + 128 B rows
#define STAGE_BYTES (STAGE_ROWS * ROW_B)    // 20480 B
#define S_          5
#define SMEM_DYN    (S_ * STAGE_BYTES)      // 102400 B
#define NCHUNK_     (C_ / BK_)              // 16

// load one BK=32 chunk of A[128xBK] + B[128xBK] into stage `st`
// 1024 cp16 total (8 per thread of 128). combined row: 0..127 A, 128..255 B.
__device__ __forceinline__ void load_chunk(uint32_t dsm, int st,
                                           const __nv_bfloat16* Ag,
                                           const __nv_bfloat16* Bg,
                                           int ko, int tid) {
    const uint32_t base = dsm + st * STAGE_BYTES;
    #pragma unroll
    for (int i = 0; i < 8; i++) {
        int idx = tid + i * 128;          // 0..1023
        int row = idx >> 2, chunk = idx & 3;
        const __nv_bfloat16* src = (row < 128)
            ? (Ag + (size_t)row * C_ + ko + chunk * 8)
            : (Bg + (size_t)(row - 128) * C_ + ko + chunk * 8);
        cp16(base + row * ROW_B + chunk * 16, src);
    }
}

// mainloop: 16 chunks, 5-stage pipeline, wait<3> (3 chunks stay in flight),
// one barrier per chunk. acc[4][8][4] per thread (warp tile 64x64, warps 2x2)
__device__ __forceinline__ void gemm_mainloop(uint32_t dsm,
                                              const __nv_bfloat16* Ag,
                                              const __nv_bfloat16* Bg,
                                              float acc[4][8][4]) {
    const int tid = threadIdx.x, lane = tid & 31, warp = tid >> 5;
    const int wm = warp >> 1, wn = warp & 1;     // 2 x 2

    const uint32_t aBase = dsm + (wm * 64 + (lane & 15)) * ROW_B + ((lane >> 4) << 4);
    const uint32_t bBase = dsm + 128 * ROW_B
                         + (wn * 64 + ((lane >> 4) & 1) * 8 + (lane & 7)) * ROW_B
                         + (((lane >> 3) & 1) << 4);

    // prologue: chunks 0..3 -> stages 0..3
    load_chunk(dsm, 0, Ag, Bg, 0, tid);
    cp_commit();
    load_chunk(dsm, 1, Ag, Bg, BK_, tid);
    cp_commit();
    load_chunk(dsm, 2, Ag, Bg, 2 * BK_, tid);
    cp_commit();
    load_chunk(dsm, 3, Ag, Bg, 3 * BK_, tid);
    cp_commit();

    int s = 0;                 // stage of chunk kc
    int sl = 4;                // stage for chunk kc+4
    for (int kc = 0; kc < NCHUNK_; kc++) {
        cp_wait<3>();            // chunk kc landed (3 newer groups may be in flight)
        __syncthreads();         // publish; stage being refilled was consumed last iter
        if (kc < NCHUNK_ - 4) load_chunk(dsm, sl, Ag, Bg, (kc + 4) * BK_, tid);
        cp_commit();             // uniform group accounting (empty groups in tail)

        const uint32_t stoff = s * STAGE_BYTES;
        #pragma unroll
        for (int ks = 0; ks < 2; ks++) {
            uint32_t a[4][4], bb[4][4];
            #pragma unroll
            for (int mi = 0; mi < 4; mi++)
                ldsm4(a[mi], aBase + stoff + (mi * 16) * ROW_B + ks * 32);
            #pragma unroll
            for (int p = 0; p < 4; p++)
                ldsm4(bb[p], bBase + stoff + (p * 16) * ROW_B + ks * 32);
            #pragma unroll
            for (int mi = 0; mi < 4; mi++)
                #pragma unroll
                for (int nt = 0; nt < 8; nt++)
                    mma16816(acc[mi][nt], a[mi][0], a[mi][1], a[mi][2], a[mi][3],
                             bb[nt >> 1][(nt & 1) * 2], bb[nt >> 1][(nt & 1) * 2 + 1]);
        }
        s = (s == S_ - 1) ? 0 : s + 1;
        sl = (sl == S_ - 1) ? 0 : sl + 1;
    }
}

// ---------------- K1: QKV GEMM  [32768,512] x [512,1536] ----------------
__global__ __launch_bounds__(128, 2) void qkv_kernel(const float* __restrict__ bq,
                                                     const float* __restrict__ bk,
                                                     const float* __restrict__ bv) {
    extern __shared__ char dyn[];
    const int tid = threadIdx.x, lane = tid & 31, warp = tid >> 5;
    const int g = lane >> 2, tg = lane & 3;
    const int wm = warp >> 1, wn = warp & 1;
    const int mbase = blockIdx.y * 128, nbase = blockIdx.x * 128;

    const __nv_bfloat16* Ag = g_xw + (size_t)mbase * C_;
    const __nv_bfloat16* Bg = g_wT + (size_t)nbase * C_;

    float acc[4][8][4];
    #pragma unroll
    for (int mi = 0; mi < 4; mi++)
        #pragma unroll
        for (int nt = 0; nt < 8; nt++)
            #pragma unroll
            for (int e = 0; e < 4; e++) acc[mi][nt][e] = 0.f;

    gemm_mainloop(smem_u32(dyn), Ag, Bg, acc);

    #pragma unroll
    for (int mi = 0; mi < 4; mi++) {
        int row = mbase + wm * 64 + mi * 16 + g;
        #pragma unroll
        for (int nt = 0; nt < 8; nt++) {
            int col = nbase + wn * 64 + nt * 8 + 2 * tg;
            int sel = col >> 9, ci = col & 511;
            const float* bias = (sel == 0) ? bq : (sel == 1) ? bk : bv;
            float b0f = bias[ci], b1f = bias[ci + 1];
            *reinterpret_cast<uint32_t*>(g_qkv + (size_t)row * N_QKV + col) =
                pack_bf16(acc[mi][nt][0] + b0f, acc[mi][nt][1] + b1f);
            *reinterpret_cast<uint32_t*>(g_qkv + (size_t)(row + 8) * N_QKV + col) =
                pack_bf16(acc[mi][nt][2] + b0f, acc[mi][nt][3] + b1f);
        }
    }
}

// ---------------- K3: output projection + bias + residual (inverse roll scatter) ----------------
__global__ __launch_bounds__(128, 2) void proj_kernel(const float* __restrict__ x,
                                                      const float* __restrict__ bo,
                                                      float* __restrict__ out) {
    extern __shared__ char dyn[];
    const int tid = threadIdx.x, lane = tid & 31, warp = tid >> 5;
    const int g = lane >> 2, tg = lane & 3;
    const int wm = warp >> 1, wn = warp & 1;
    const int mbase = blockIdx.y * 128, nbase = blockIdx.x * 128;

    const __nv_bfloat16* Ag = g_o + (size_t)mbase * C_;
    const __nv_bfloat16* Bg = g_woT + (size_t)nbase * C_;

    float acc[4][8][4];
    #pragma unroll
    for (int mi = 0; mi < 4; mi++)
        #pragma unroll
        for (int nt = 0; nt < 8; nt++)
            #pragma unroll
            for (int e = 0; e < 4; e++) acc[mi][nt][e] = 0.f;

    gemm_mainloop(smem_u32(dyn), Ag, Bg, acc);

    #pragma unroll
    for (int mi = 0; mi < 4; mi++) {
        #pragma unroll
        for (int half = 0; half < 2; half++) {
            int row = mbase + wm * 64 + mi * 16 + g + half * 8;
            int win = row >> 6, t = row & 63;
            int b = win >> 6, wh = (win >> 3) & 7, ww = win & 7;
            int i = t >> 3, j = t & 7;
            int r  = (wh * 8 + i + 4) & 63;
            int cc = (ww * 8 + j + 4) & 63;
            size_t off = (size_t)((b * 64 + r) * 64 + cc) * C_;
            #pragma unroll
            for (int nt = 0; nt < 8; nt++) {
                int col = nbase + wn * 64 + nt * 8 + 2 * tg;
                float2 xr = *reinterpret_cast<const float2*>(x + off + col);
                float2 o;
                o.x = acc[mi][nt][2 * half + 0] + bo[col]     + xr.x;
                o.y = acc[mi][nt][2 * half + 1] + bo[col + 1] + xr.y;
                *reinterpret_cast<float2*>(out + off + col) = o;
            }
        }
    }
}

// ---------------- K2: attention per (window, head) — cp.async loads (R7) ----------------
__global__ __launch_bounds__(128) void attn_kernel() {
    __shared__ __nv_bfloat16 Qs[64 * 72];
    __shared__ __nv_bfloat16 Ks[64 * 72];
    __shared__ __nv_bfloat16 Vs[64 * 72];

    const int nh = blockIdx.x;
    const int n = nh >> 3, h = nh & 7;
    const int tid = threadIdx.x, lane = tid & 31, warp = tid >> 5;
    const int g = lane >> 2, tg = lane & 3;

    const __nv_bfloat16* src = g_qkv + (size_t)(n * 64) * N_QKV + h * 64;
    const uint32_t qS = smem_u32(Qs), kS = smem_u32(Ks), vS = smem_u32(Vs);
    #pragma unroll
    for (int e = 0; e < 4; e++) {
        int it = tid + e * 128;
        int row = it >> 3, seg = it & 7;
        const __nv_bfloat16* rp = src + (size_t)row * N_QKV + seg * 8;
        cp16(qS + row * 144 + seg * 16, rp);
        cp16(kS + row * 144 + seg * 16, rp + 512);
        cp16(vS + row * 144 + seg * 16, rp + 1024);
    }
    cp_commit();
    cp_wait<0>();
    __syncthreads();

    const uint32_t qB = qS + (warp * 16 + (lane & 15)) * 144 + ((lane >> 4) << 4);
    const uint32_t kB = kS + ((((lane >> 4) & 1) * 8 + (lane & 7)) * 144) + (((lane >> 3) & 1) << 4);
    const uint32_t vB = vS + (((lane & 7) + ((lane >> 3) & 1) * 8) * 144) + (((lane >> 4) & 1) << 4);

    float sc[8][4];
    #pragma unroll
    for (int nt = 0; nt < 8; nt++) { sc[nt][0]=0.f; sc[nt][1]=0.f; sc[nt][2]=0.f; sc[nt][3]=0.f; }
    #pragma unroll
    for (int ks = 0; ks < 4; ks++) {
        uint32_t a[4], bb[4][4];
        ldsm4(a, qB + ks * 32);
        #pragma unroll
        for (int p = 0; p < 4; p++)
            ldsm4(bb[p], kB + (p * 16) * 144 + ks * 32);
        #pragma unroll
        for (int nt = 0; nt < 8; nt++)
            mma16816(sc[nt], a[0], a[1], a[2], a[3],
                     bb[nt >> 1][(nt & 1) * 2], bb[nt >> 1][(nt & 1) * 2 + 1]);
    }

    float mx0 = -1e30f, mx1 = -1e30f;
    #pragma unroll
    for (int nt = 0; nt < 8; nt++) {
        mx0 = fmaxf(mx0, fmaxf(sc[nt][0], sc[nt][1]));
        mx1 = fmaxf(mx1, fmaxf(sc[nt][2], sc[nt][3]));
    }
    mx0 = fmaxf(mx0, __shfl_xor_sync(0xffffffff, mx0, 1));
    mx0 = fmaxf(mx0, __shfl_xor_sync(0xffffffff, mx0, 2));
    mx1 = fmaxf(mx1, __shfl_xor_sync(0xffffffff, mx1, 1));
    mx1 = fmaxf(mx1, __shfl_xor_sync(0xffffffff, mx1, 2));
    float s0 = 0.f, s1 = 0.f;
    #pragma unroll
    for (int nt = 0; nt < 8; nt++) {
        sc[nt][0] = __expf((sc[nt][0] - mx0) * SCALE_);
        sc[nt][1] = __expf((sc[nt][1] - mx0) * SCALE_);
        sc[nt][2] = __expf((sc[nt][2] - mx1) * SCALE_);
        sc[nt][3] = __expf((sc[nt][3] - mx1) * SCALE_);
        s0 += sc[nt][0] + sc[nt][1];
        s1 += sc[nt][2] + sc[nt][3];
    }
    s0 += __shfl_xor_sync(0xffffffff, s0, 1);
    s0 += __shfl_xor_sync(0xffffffff, s0, 2);
    s1 += __shfl_xor_sync(0xffffffff, s1, 1);
    s1 += __shfl_xor_sync(0xffffffff, s1, 2);
    const float i0 = 1.f / s0, i1 = 1.f / s1;

    uint32_t pa[8][2];
    #pragma unroll
    for (int nt = 0; nt < 8; nt++) {
        pa[nt][0] = pack_bf16(sc[nt][0] * i0, sc[nt][1] * i0);
        pa[nt][1] = pack_bf16(sc[nt][2] * i1, sc[nt][3] * i1);
    }

    float oc[8][4];
    #pragma unroll
    for (int nt = 0; nt < 8; nt++) { oc[nt][0]=0.f; oc[nt][1]=0.f; oc[nt][2]=0.f; oc[nt][3]=0.f; }
    #pragma unroll
    for (int ks = 0; ks < 4; ks++) {
        uint32_t bb[4][4];
        #pragma unroll
        for (int p = 0; p < 4; p++)
            ldsm4t(bb[p], vB + (ks * 16) * 144 + p * 32);
        uint32_t a0 = pa[2 * ks][0], a1 = pa[2 * ks][1];
        uint32_t a2 = pa[2 * ks + 1][0], a3 = pa[2 * ks + 1][1];
        #pragma unroll
        for (int nt = 0; nt < 8; nt++)
            mma16816(oc[nt], a0, a1, a2, a3,
                     bb[nt >> 1][(nt & 1) * 2], bb[nt >> 1][(nt & 1) * 2 + 1]);
    }

    const int r0 = warp * 16 + g;
    __nv_bfloat16* dst = g_o + (size_t)(n * 64) * C_ + h * 64;
    #pragma unroll
    for (int nt = 0; nt < 8; nt++) {
        int dcol = nt * 8 + 2 * tg;
        *reinterpret_cast<uint32_t*>(dst + (size_t)r0 * C_ + dcol)       = pack_bf16(oc[nt][0], oc[nt][1]);
        *reinterpret_cast<uint32_t*>(dst + (size_t)(r0 + 8) * C_ + dcol) = pack_bf16(oc[nt][2], oc[nt][3]);
    }
}

// ---------------- launch ----------------
extern "C" void kernel_launch(void* const* d_in, const int* in_sizes, int n_in,
                              void* d_out, int out_size) {
    const float* x  = (const float*)d_in[0];
    const float* wq = (const float*)d_in[1];
    const float* bq = (const float*)d_in[2];
    const float* wk = (const float*)d_in[3];
    const float* bk = (const float*)d_in[4];
    const float* wv = (const float*)d_in[5];
    const float* bv = (const float*)d_in[6];
    const float* wo = (const float*)d_in[7];
    const float* bo = (const float*)d_in[8];
    float* out = (float*)d_out;

    cudaFuncSetAttribute(qkv_kernel,  cudaFuncAttributeMaxDynamicSharedMemorySize, SMEM_DYN);
    cudaFuncSetAttribute(proj_kernel, cudaFuncAttributeMaxDynamicSharedMemorySize, SMEM_DYN);

    prep_kernel<<<17408, 256>>>(x, wq, wk, wv, wo);
    dim3 g1(12, 256);
    qkv_kernel<<<g1, 128, SMEM_DYN>>>(bq, bk, bv);
    attn_kernel<<<NWIN * NH_, 128>>>();
    dim3 g3(4, 256);
    proj_kernel<<<g3, 128, SMEM_DYN>>>(x, bo, out);
}

// round 9
// speedup vs baseline: 1.0889x; 1.0889x over previous
#include <cuda_runtime.h>
#include <cuda_bf16.h>
#include <stdint.h>

#define NWIN   512
#define T_     64
#define C_     512
#define NH_    8
#define D_     64
#define MROWS  32768        // NWIN * T_
#define N_QKV  1536
#define SCALE_ 0.125f

// ---------------- scratch ----------------
__device__ __nv_bfloat16 g_xw [MROWS * C_];      // gathered+rolled x, bf16
__device__ __nv_bfloat16 g_qkv[MROWS * N_QKV];   // Q|K|V concat
__device__ __nv_bfloat16 g_o  [MROWS * C_];      // attention out
__device__ __nv_bfloat16 g_wT [N_QKV * C_];      // [out col][k]
__device__ __nv_bfloat16 g_woT[C_ * C_];         // [out c][k=hd]

// ---------------- asm helpers ----------------
__device__ __forceinline__ void mma16816(float* c, uint32_t a0, uint32_t a1, uint32_t a2, uint32_t a3,
                                         uint32_t b0, uint32_t b1) {
    asm volatile(
        "mma.sync.aligned.m16n8k16.row.col.f32.bf16.bf16.f32 "
        "{%0,%1,%2,%3}, {%4,%5,%6,%7}, {%8,%9}, {%0,%1,%2,%3};"
        : "+f"(c[0]), "+f"(c[1]), "+f"(c[2]), "+f"(c[3])
        : "r"(a0), "r"(a1), "r"(a2), "r"(a3), "r"(b0), "r"(b1));
}
__device__ __forceinline__ void ldsm4(uint32_t* r, uint32_t addr) {
    asm volatile("ldmatrix.sync.aligned.m8n8.x4.shared.b16 {%0,%1,%2,%3}, [%4];"
                 : "=r"(r[0]), "=r"(r[1]), "=r"(r[2]), "=r"(r[3]) : "r"(addr));
}
__device__ __forceinline__ void ldsm4t(uint32_t* r, uint32_t addr) {
    asm volatile("ldmatrix.sync.aligned.m8n8.x4.trans.shared.b16 {%0,%1,%2,%3}, [%4];"
                 : "=r"(r[0]), "=r"(r[1]), "=r"(r[2]), "=r"(r[3]) : "r"(addr));
}
__device__ __forceinline__ void cp16(uint32_t smem_dst, const void* gmem_src) {
    asm volatile("cp.async.cg.shared.global [%0], [%1], 16;" :: "r"(smem_dst), "l"(gmem_src));
}
__device__ __forceinline__ void cp_commit() { asm volatile("cp.async.commit_group;"); }
template<int N> __device__ __forceinline__ void cp_wait() { asm volatile("cp.async.wait_group %0;" :: "n"(N)); }
__device__ __forceinline__ uint32_t smem_u32(const void* p) {
    return (uint32_t)__cvta_generic_to_shared(p);
}
__device__ __forceinline__ uint32_t pack_bf16(float a, float b) {
    __nv_bfloat162 t = __floats2bfloat162_rn(a, b);
    return *reinterpret_cast<uint32_t*>(&t);
}

// XOR-swizzled address of 16B chunk c (0..3) of logical 64B row `row` (0..255)
// within a stage. Two logical rows per 128B physical row; chunk permuted by
// phys-row low bits. Conflict-free for ldsm.x4 reads and cp.async stores.
__device__ __forceinline__ uint32_t sw_addr(int row, int c) {
    return (uint32_t)(((row >> 1) << 7) + (((((row & 1) << 2) | c) ^ ((row >> 1) & 7)) << 4));
}

// ---------------- K0: fused weight-convert + input-gather ----------------
__global__ __launch_bounds__(256) void prep_kernel(const float* __restrict__ x,
                                                   const float* __restrict__ wq,
                                                   const float* __restrict__ wk,
                                                   const float* __restrict__ wv,
                                                   const float* __restrict__ wo) {
    if (blockIdx.x < 1024) {
        int idx = blockIdx.x * 256 + threadIdx.x;     // 0..262143
        int r = idx >> 9;
        int j = idx & 511;
        g_wT[j * C_ + r]          = __float2bfloat16(wq[idx]);
        g_wT[(512 + j) * C_ + r]  = __float2bfloat16(wk[idx]);
        g_wT[(1024 + j) * C_ + r] = __float2bfloat16(wv[idx]);
        g_woT[j * C_ + r]         = __float2bfloat16(wo[idx]);
    } else {
        int idx = (blockIdx.x - 1024) * 256 + threadIdx.x;  // 0..4194303
        int row = idx >> 7;
        int ch  = idx & 127;
        int win = row >> 6, t = row & 63;
        int b = win >> 6, wh = (win >> 3) & 7, ww = win & 7;
        int i = t >> 3, j = t & 7;
        int r  = (wh * 8 + i + 4) & 63;
        int cc = (ww * 8 + j + 4) & 63;
        float4 f = *reinterpret_cast<const float4*>(x + (((b * 64 + r) * 64 + cc) << 9) + ch * 4);
        uint2 o;
        o.x = pack_bf16(f.x, f.y);
        o.y = pack_bf16(f.z, f.w);
        *reinterpret_cast<uint2*>(g_xw + row * C_ + ch * 4) = o;
    }
}

// ---------------- GEMM config: BM=128, BN=128, BK=32, S=5, 128 threads ----------------
// 4 warps 2x2 -> warp tile 64x64. Swizzled stage: 256 rows x 64B = 16KB.
#define BK_         32
#define STAGE_BYTES 16384
#define S_          5
#define SMEM_DYN    (S_ * STAGE_BYTES)      // 81920 B
#define NCHUNK_     (C_ / BK_)              // 16

// load one BK=32 chunk of A[128xBK] + B[128xBK] into stage `st` (swizzled).
// 1024 cp16 total (8 per thread of 128). logical row: 0..127 A, 128..255 B.
__device__ __forceinline__ void load_chunk(uint32_t dsm, int st,
                                           const __nv_bfloat16* Ag,
                                           const __nv_bfloat16* Bg,
                                           int ko, int tid) {
    const uint32_t base = dsm + st * STAGE_BYTES;
    #pragma unroll
    for (int i = 0; i < 8; i++) {
        int idx = tid + i * 128;          // 0..1023
        int row = idx >> 2, c = idx & 3;
        const __nv_bfloat16* src = (row < 128)
            ? (Ag + (size_t)row * C_ + ko + c * 8)
            : (Bg + (size_t)(row - 128) * C_ + ko + c * 8);
        cp16(base + sw_addr(row, c), src);
    }
}

// mainloop: 16 chunks, 5-stage pipeline, wait<3>, one barrier per chunk.
// acc[4][8][4] per thread (warp tile 64x64, warps 2x2)
__device__ __forceinline__ void gemm_mainloop(uint32_t dsm,
                                              const __nv_bfloat16* Ag,
                                              const __nv_bfloat16* Bg,
                                              float acc[4][8][4]) {
    const int tid = threadIdx.x, lane = tid & 31, warp = tid >> 5;
    const int wm = warp >> 1, wn = warp & 1;     // 2 x 2

    // per-lane swizzled fragment offsets (within stage); +1024B per 16 rows.
    const int r_a = wm * 64 + (lane & 15);
    const int c_a = lane >> 4;                         // 0..1
    const uint32_t aOff0 = sw_addr(r_a, c_a);
    const uint32_t aOff1 = sw_addr(r_a, c_a + 2);
    const int r_b = 128 + wn * 64 + ((lane >> 4) & 1) * 8 + (lane & 7);
    const int c_b = (lane >> 3) & 1;
    const uint32_t bOff0 = sw_addr(r_b, c_b);
    const uint32_t bOff1 = sw_addr(r_b, c_b + 2);

    // prologue: chunks 0..3 -> stages 0..3
    load_chunk(dsm, 0, Ag, Bg, 0, tid);
    cp_commit();
    load_chunk(dsm, 1, Ag, Bg, BK_, tid);
    cp_commit();
    load_chunk(dsm, 2, Ag, Bg, 2 * BK_, tid);
    cp_commit();
    load_chunk(dsm, 3, Ag, Bg, 3 * BK_, tid);
    cp_commit();

    int s = 0;                 // stage of chunk kc
    int sl = 4;                // stage for chunk kc+4
    for (int kc = 0; kc < NCHUNK_; kc++) {
        cp_wait<3>();
        __syncthreads();
        if (kc < NCHUNK_ - 4) load_chunk(dsm, sl, Ag, Bg, (kc + 4) * BK_, tid);
        cp_commit();

        const uint32_t stbase = dsm + s * STAGE_BYTES;
        #pragma unroll
        for (int ks = 0; ks < 2; ks++) {
            const uint32_t aOff = stbase + (ks ? aOff1 : aOff0);
            const uint32_t bOff = stbase + (ks ? bOff1 : bOff0);
            uint32_t a[4][4], bb[4][4];
            #pragma unroll
            for (int mi = 0; mi < 4; mi++)
                ldsm4(a[mi], aOff + mi * 1024);
            #pragma unroll
            for (int p = 0; p < 4; p++)
                ldsm4(bb[p], bOff + p * 1024);
            #pragma unroll
            for (int mi = 0; mi < 4; mi++)
                #pragma unroll
                for (int nt = 0; nt < 8; nt++)
                    mma16816(acc[mi][nt], a[mi][0], a[mi][1], a[mi][2], a[mi][3],
                             bb[nt >> 1][(nt & 1) * 2], bb[nt >> 1][(nt & 1) * 2 + 1]);
        }
        s = (s == S_ - 1) ? 0 : s + 1;
        sl = (sl == S_ - 1) ? 0 : sl + 1;
    }
}

// ---------------- K1: QKV GEMM  [32768,512] x [512,1536] ----------------
__global__ __launch_bounds__(128, 2) void qkv_kernel(const float* __restrict__ bq,
                                                     const float* __restrict__ bk,
                                                     const float* __restrict__ bv) {
    extern __shared__ char dyn[];
    const int tid = threadIdx.x, lane = tid & 31, warp = tid >> 5;
    const int g = lane >> 2, tg = lane & 3;
    const int wm = warp >> 1, wn = warp & 1;
    const int mbase = blockIdx.y * 128, nbase = blockIdx.x * 128;

    const __nv_bfloat16* Ag = g_xw + (size_t)mbase * C_;
    const __nv_bfloat16* Bg = g_wT + (size_t)nbase * C_;

    float acc[4][8][4];
    #pragma unroll
    for (int mi = 0; mi < 4; mi++)
        #pragma unroll
        for (int nt = 0; nt < 8; nt++)
            #pragma unroll
            for (int e = 0; e < 4; e++) acc[mi][nt][e] = 0.f;

    gemm_mainloop(smem_u32(dyn), Ag, Bg, acc);

    #pragma unroll
    for (int mi = 0; mi < 4; mi++) {
        int row = mbase + wm * 64 + mi * 16 + g;
        #pragma unroll
        for (int nt = 0; nt < 8; nt++) {
            int col = nbase + wn * 64 + nt * 8 + 2 * tg;
            int sel = col >> 9, ci = col & 511;
            const float* bias = (sel == 0) ? bq : (sel == 1) ? bk : bv;
            float b0f = bias[ci], b1f = bias[ci + 1];
            *reinterpret_cast<uint32_t*>(g_qkv + (size_t)row * N_QKV + col) =
                pack_bf16(acc[mi][nt][0] + b0f, acc[mi][nt][1] + b1f);
            *reinterpret_cast<uint32_t*>(g_qkv + (size_t)(row + 8) * N_QKV + col) =
                pack_bf16(acc[mi][nt][2] + b0f, acc[mi][nt][3] + b1f);
        }
    }
}

// ---------------- K3: output projection + bias + residual (inverse roll scatter) ----------------
__global__ __launch_bounds__(128, 2) void proj_kernel(const float* __restrict__ x,
                                                      const float* __restrict__ bo,
                                                      float* __restrict__ out) {
    extern __shared__ char dyn[];
    const int tid = threadIdx.x, lane = tid & 31, warp = tid >> 5;
    const int g = lane >> 2, tg = lane & 3;
    const int wm = warp >> 1, wn = warp & 1;
    const int mbase = blockIdx.y * 128, nbase = blockIdx.x * 128;

    const __nv_bfloat16* Ag = g_o + (size_t)mbase * C_;
    const __nv_bfloat16* Bg = g_woT + (size_t)nbase * C_;

    float acc[4][8][4];
    #pragma unroll
    for (int mi = 0; mi < 4; mi++)
        #pragma unroll
        for (int nt = 0; nt < 8; nt++)
            #pragma unroll
            for (int e = 0; e < 4; e++) acc[mi][nt][e] = 0.f;

    gemm_mainloop(smem_u32(dyn), Ag, Bg, acc);

    #pragma unroll
    for (int mi = 0; mi < 4; mi++) {
        #pragma unroll
        for (int half = 0; half < 2; half++) {
            int row = mbase + wm * 64 + mi * 16 + g + half * 8;
            int win = row >> 6, t = row & 63;
            int b = win >> 6, wh = (win >> 3) & 7, ww = win & 7;
            int i = t >> 3, j = t & 7;
            int r  = (wh * 8 + i + 4) & 63;
            int cc = (ww * 8 + j + 4) & 63;
            size_t off = (size_t)((b * 64 + r) * 64 + cc) * C_;
            #pragma unroll
            for (int nt = 0; nt < 8; nt++) {
                int col = nbase + wn * 64 + nt * 8 + 2 * tg;
                float2 xr = *reinterpret_cast<const float2*>(x + off + col);
                float2 o;
                o.x = acc[mi][nt][2 * half + 0] + bo[col]     + xr.x;
                o.y = acc[mi][nt][2 * half + 1] + bo[col + 1] + xr.y;
                *reinterpret_cast<float2*>(out + off + col) = o;
            }
        }
    }
}

// ---------------- K2: attention per (window, head) ----------------
__global__ __launch_bounds__(128) void attn_kernel() {
    __shared__ __nv_bfloat16 Qs[64 * 72];
    __shared__ __nv_bfloat16 Ks[64 * 72];
    __shared__ __nv_bfloat16 Vs[64 * 72];

    const int nh = blockIdx.x;
    const int n = nh >> 3, h = nh & 7;
    const int tid = threadIdx.x, lane = tid & 31, warp = tid >> 5;
    const int g = lane >> 2, tg = lane & 3;

    const __nv_bfloat16* src = g_qkv + (size_t)(n * 64) * N_QKV + h * 64;
    const uint32_t qS = smem_u32(Qs), kS = smem_u32(Ks), vS = smem_u32(Vs);
    #pragma unroll
    for (int e = 0; e < 4; e++) {
        int it = tid + e * 128;
        int row = it >> 3, seg = it & 7;
        const __nv_bfloat16* rp = src + (size_t)row * N_QKV + seg * 8;
        cp16(qS + row * 144 + seg * 16, rp);
        cp16(kS + row * 144 + seg * 16, rp + 512);
        cp16(vS + row * 144 + seg * 16, rp + 1024);
    }
    cp_commit();
    cp_wait<0>();
    __syncthreads();

    const uint32_t qB = qS + (warp * 16 + (lane & 15)) * 144 + ((lane >> 4) << 4);
    const uint32_t kB = kS + ((((lane >> 4) & 1) * 8 + (lane & 7)) * 144) + (((lane >> 3) & 1) << 4);
    const uint32_t vB = vS + (((lane & 7) + ((lane >> 3) & 1) * 8) * 144) + (((lane >> 4) & 1) << 4);

    float sc[8][4];
    #pragma unroll
    for (int nt = 0; nt < 8; nt++) { sc[nt][0]=0.f; sc[nt][1]=0.f; sc[nt][2]=0.f; sc[nt][3]=0.f; }
    #pragma unroll
    for (int ks = 0; ks < 4; ks++) {
        uint32_t a[4], bb[4][4];
        ldsm4(a, qB + ks * 32);
        #pragma unroll
        for (int p = 0; p < 4; p++)
            ldsm4(bb[p], kB + (p * 16) * 144 + ks * 32);
        #pragma unroll
        for (int nt = 0; nt < 8; nt++)
            mma16816(sc[nt], a[0], a[1], a[2], a[3],
                     bb[nt >> 1][(nt & 1) * 2], bb[nt >> 1][(nt & 1) * 2 + 1]);
    }

    float mx0 = -1e30f, mx1 = -1e30f;
    #pragma unroll
    for (int nt = 0; nt < 8; nt++) {
        mx0 = fmaxf(mx0, fmaxf(sc[nt][0], sc[nt][1]));
        mx1 = fmaxf(mx1, fmaxf(sc[nt][2], sc[nt][3]));
    }
    mx0 = fmaxf(mx0, __shfl_xor_sync(0xffffffff, mx0, 1));
    mx0 = fmaxf(mx0, __shfl_xor_sync(0xffffffff, mx0, 2));
    mx1 = fmaxf(mx1, __shfl_xor_sync(0xffffffff, mx1, 1));
    mx1 = fmaxf(mx1, __shfl_xor_sync(0xffffffff, mx1, 2));
    float s0 = 0.f, s1 = 0.f;
    #pragma unroll
    for (int nt = 0; nt < 8; nt++) {
        sc[nt][0] = __expf((sc[nt][0] - mx0) * SCALE_);
        sc[nt][1] = __expf((sc[nt][1] - mx0) * SCALE_);
        sc[nt][2] = __expf((sc[nt][2] - mx1) * SCALE_);
        sc[nt][3] = __expf((sc[nt][3] - mx1) * SCALE_);
        s0 += sc[nt][0] + sc[nt][1];
        s1 += sc[nt][2] + sc[nt][3];
    }
    s0 += __shfl_xor_sync(0xffffffff, s0, 1);
    s0 += __shfl_xor_sync(0xffffffff, s0, 2);
    s1 += __shfl_xor_sync(0xffffffff, s1, 1);
    s1 += __shfl_xor_sync(0xffffffff, s1, 2);
    const float i0 = 1.f / s0, i1 = 1.f / s1;

    uint32_t pa[8][2];
    #pragma unroll
    for (int nt = 0; nt < 8; nt++) {
        pa[nt][0] = pack_bf16(sc[nt][0] * i0, sc[nt][1] * i0);
        pa[nt][1] = pack_bf16(sc[nt][2] * i1, sc[nt][3] * i1);
    }

    float oc[8][4];
    #pragma unroll
    for (int nt = 0; nt < 8; nt++) { oc[nt][0]=0.f; oc[nt][1]=0.f; oc[nt][2]=0.f; oc[nt][3]=0.f; }
    #pragma unroll
    for (int ks = 0; ks < 4; ks++) {
        uint32_t bb[4][4];
        #pragma unroll
        for (int p = 0; p < 4; p++)
            ldsm4t(bb[p], vB + (ks * 16) * 144 + p * 32);
        uint32_t a0 = pa[2 * ks][0], a1 = pa[2 * ks][1];
        uint32_t a2 = pa[2 * ks + 1][0], a3 = pa[2 * ks + 1][1];
        #pragma unroll
        for (int nt = 0; nt < 8; nt++)
            mma16816(oc[nt], a0, a1, a2, a3,
                     bb[nt >> 1][(nt & 1) * 2], bb[nt >> 1][(nt & 1) * 2 + 1]);
    }

    const int r0 = warp * 16 + g;
    __nv_bfloat16* dst = g_o + (size_t)(n * 64) * C_ + h * 64;
    #pragma unroll
    for (int nt = 0; nt < 8; nt++) {
        int dcol = nt * 8 + 2 * tg;
        *reinterpret_cast<uint32_t*>(dst + (size_t)r0 * C_ + dcol)       = pack_bf16(oc[nt][0], oc[nt][1]);
        *reinterpret_cast<uint32_t*>(dst + (size_t)(r0 + 8) * C_ + dcol) = pack_bf16(oc[nt][2], oc[nt][3]);
    }
}

// ---------------- launch ----------------
extern "C" void kernel_launch(void* const* d_in, const int* in_sizes, int n_in,
                              void* d_out, int out_size) {
    const float* x  = (const float*)d_in[0];
    const float* wq = (const float*)d_in[1];
    const float* bq = (const float*)d_in[2];
    const float* wk = (const float*)d_in[3];
    const float* bk = (const float*)d_in[4];
    const float* wv = (const float*)d_in[5];
    const float* bv = (const float*)d_in[6];
    const float* wo = (const float*)d_in[7];
    const float* bo = (const float*)d_in[8];
    float* out = (float*)d_out;

    cudaFuncSetAttribute(qkv_kernel,  cudaFuncAttributeMaxDynamicSharedMemorySize, SMEM_DYN);
    cudaFuncSetAttribute(proj_kernel, cudaFuncAttributeMaxDynamicSharedMemorySize, SMEM_DYN);

    prep_kernel<<<17408, 256>>>(x, wq, wk, wv, wo);
    dim3 g1(12, 256);
    qkv_kernel<<<g1, 128, SMEM_DYN>>>(bq, bk, bv);
    attn_kernel<<<NWIN * NH_, 128>>>();
    dim3 g3(4, 256);
    proj_kernel<<<g3, 128, SMEM_DYN>>>(x, bo, out);
}

// round 10
// speedup vs baseline: 1.0999x; 1.0101x over previous
#include <cuda_runtime.h>
#include <cuda_bf16.h>
#include <stdint.h>

#define NWIN   512
#define T_     64
#define C_     512
#define NH_    8
#define D_     64
#define MROWS  32768        // NWIN * T_
#define N_QKV  1536
#define SCALE_ 0.125f

// ---------------- scratch ----------------
__device__ __nv_bfloat16 g_xw [MROWS * C_];      // gathered+rolled x, bf16
__device__ __nv_bfloat16 g_qkv[MROWS * N_QKV];   // Q|K|V concat
__device__ __nv_bfloat16 g_o  [MROWS * C_];      // attention out
__device__ __nv_bfloat16 g_wT [N_QKV * C_];      // [out col][k]
__device__ __nv_bfloat16 g_woT[C_ * C_];         // [out c][k=hd]

// ---------------- asm helpers ----------------
__device__ __forceinline__ void mma16816(float* c, uint32_t a0, uint32_t a1, uint32_t a2, uint32_t a3,
                                         uint32_t b0, uint32_t b1) {
    asm volatile(
        "mma.sync.aligned.m16n8k16.row.col.f32.bf16.bf16.f32 "
        "{%0,%1,%2,%3}, {%4,%5,%6,%7}, {%8,%9}, {%0,%1,%2,%3};"
        : "+f"(c[0]), "+f"(c[1]), "+f"(c[2]), "+f"(c[3])
        : "r"(a0), "r"(a1), "r"(a2), "r"(a3), "r"(b0), "r"(b1));
}
__device__ __forceinline__ void ldsm4(uint32_t* r, uint32_t addr) {
    asm volatile("ldmatrix.sync.aligned.m8n8.x4.shared.b16 {%0,%1,%2,%3}, [%4];"
                 : "=r"(r[0]), "=r"(r[1]), "=r"(r[2]), "=r"(r[3]) : "r"(addr));
}
__device__ __forceinline__ void ldsm4t(uint32_t* r, uint32_t addr) {
    asm volatile("ldmatrix.sync.aligned.m8n8.x4.trans.shared.b16 {%0,%1,%2,%3}, [%4];"
                 : "=r"(r[0]), "=r"(r[1]), "=r"(r[2]), "=r"(r[3]) : "r"(addr));
}
__device__ __forceinline__ void cp16(uint32_t smem_dst, const void* gmem_src) {
    asm volatile("cp.async.cg.shared.global [%0], [%1], 16;" :: "r"(smem_dst), "l"(gmem_src));
}
__device__ __forceinline__ void cp_commit() { asm volatile("cp.async.commit_group;"); }
template<int N> __device__ __forceinline__ void cp_wait() { asm volatile("cp.async.wait_group %0;" :: "n"(N)); }
__device__ __forceinline__ uint32_t smem_u32(const void* p) {
    return (uint32_t)__cvta_generic_to_shared(p);
}
__device__ __forceinline__ uint32_t pack_bf16(float a, float b) {
    __nv_bfloat162 t = __floats2bfloat162_rn(a, b);
    return *reinterpret_cast<uint32_t*>(&t);
}

// XOR-swizzled address of 16B chunk c (0..3) of logical 64B row `row` (0..255)
// within a stage. Conflict-free for ldsm.x4 reads and cp.async stores.
__device__ __forceinline__ uint32_t sw_addr(int row, int c) {
    return (uint32_t)(((row >> 1) << 7) + (((((row & 1) << 2) | c) ^ ((row >> 1) & 7)) << 4));
}

// ---------------- K0: fused weight-convert + input-gather ----------------
__global__ __launch_bounds__(256) void prep_kernel(const float* __restrict__ x,
                                                   const float* __restrict__ wq,
                                                   const float* __restrict__ wk,
                                                   const float* __restrict__ wv,
                                                   const float* __restrict__ wo) {
    if (blockIdx.x < 1024) {
        int idx = blockIdx.x * 256 + threadIdx.x;     // 0..262143
        int r = idx >> 9;
        int j = idx & 511;
        g_wT[j * C_ + r]          = __float2bfloat16(wq[idx]);
        g_wT[(512 + j) * C_ + r]  = __float2bfloat16(wk[idx]);
        g_wT[(1024 + j) * C_ + r] = __float2bfloat16(wv[idx]);
        g_woT[j * C_ + r]         = __float2bfloat16(wo[idx]);
    } else {
        int idx = (blockIdx.x - 1024) * 256 + threadIdx.x;  // 0..4194303
        int row = idx >> 7;
        int ch  = idx & 127;
        int win = row >> 6, t = row & 63;
        int b = win >> 6, wh = (win >> 3) & 7, ww = win & 7;
        int i = t >> 3, j = t & 7;
        int r  = (wh * 8 + i + 4) & 63;
        int cc = (ww * 8 + j + 4) & 63;
        float4 f = *reinterpret_cast<const float4*>(x + (((b * 64 + r) * 64 + cc) << 9) + ch * 4);
        uint2 o;
        o.x = pack_bf16(f.x, f.y);
        o.y = pack_bf16(f.z, f.w);
        *reinterpret_cast<uint2*>(g_xw + row * C_ + ch * 4) = o;
    }
}

// ---------------- GEMM config: BM=128, BN=128, BK=32, S=5, 256 threads ----------------
// 8 warps 4x2 -> warp tile 32x64, acc 64 regs. Swizzled stage: 256 rows x 64B = 16KB.
#define BK_         32
#define STAGE_BYTES 16384
#define S_          5
#define SMEM_DYN    (S_ * STAGE_BYTES)      // 81920 B
#define NCHUNK_     (C_ / BK_)              // 16

// load one BK=32 chunk of A[128xBK] + B[128xBK] into stage `st` (swizzled).
// 1024 cp16 total (4 per thread of 256). logical row: 0..127 A, 128..255 B.
__device__ __forceinline__ void load_chunk(uint32_t dsm, int st,
                                           const __nv_bfloat16* Ag,
                                           const __nv_bfloat16* Bg,
                                           int ko, int tid) {
    const uint32_t base = dsm + st * STAGE_BYTES;
    #pragma unroll
    for (int i = 0; i < 4; i++) {
        int idx = tid + i * 256;          // 0..1023
        int row = idx >> 2, c = idx & 3;
        const __nv_bfloat16* src = (row < 128)
            ? (Ag + (size_t)row * C_ + ko + c * 8)
            : (Bg + (size_t)(row - 128) * C_ + ko + c * 8);
        cp16(base + sw_addr(row, c), src);
    }
}

// mainloop: 16 chunks, 5-stage pipeline, wait<3>, one barrier per chunk.
// acc[2][8][4] per thread (warp tile 32x64, warps 4x2)
__device__ __forceinline__ void gemm_mainloop(uint32_t dsm,
                                              const __nv_bfloat16* Ag,
                                              const __nv_bfloat16* Bg,
                                              float acc[2][8][4]) {
    const int tid = threadIdx.x, lane = tid & 31, warp = tid >> 5;
    const int wm = warp >> 1, wn = warp & 1;     // 4 x 2

    // per-lane swizzled fragment offsets (within stage); +1024B per 16 rows.
    const int r_a = wm * 32 + (lane & 15);
    const int c_a = lane >> 4;                         // 0..1
    const uint32_t aOff0 = sw_addr(r_a, c_a);
    const uint32_t aOff1 = sw_addr(r_a, c_a + 2);
    const int r_b = 128 + wn * 64 + ((lane >> 4) & 1) * 8 + (lane & 7);
    const int c_b = (lane >> 3) & 1;
    const uint32_t bOff0 = sw_addr(r_b, c_b);
    const uint32_t bOff1 = sw_addr(r_b, c_b + 2);

    // prologue: chunks 0..3 -> stages 0..3
    load_chunk(dsm, 0, Ag, Bg, 0, tid);
    cp_commit();
    load_chunk(dsm, 1, Ag, Bg, BK_, tid);
    cp_commit();
    load_chunk(dsm, 2, Ag, Bg, 2 * BK_, tid);
    cp_commit();
    load_chunk(dsm, 3, Ag, Bg, 3 * BK_, tid);
    cp_commit();

    int s = 0;                 // stage of chunk kc
    int sl = 4;                // stage for chunk kc+4
    for (int kc = 0; kc < NCHUNK_; kc++) {
        cp_wait<3>();
        __syncthreads();
        if (kc < NCHUNK_ - 4) load_chunk(dsm, sl, Ag, Bg, (kc + 4) * BK_, tid);
        cp_commit();

        const uint32_t stbase = dsm + s * STAGE_BYTES;
        #pragma unroll
        for (int ks = 0; ks < 2; ks++) {
            const uint32_t aOff = stbase + (ks ? aOff1 : aOff0);
            const uint32_t bOff = stbase + (ks ? bOff1 : bOff0);
            uint32_t a[2][4], bb[4][4];
            #pragma unroll
            for (int mi = 0; mi < 2; mi++)
                ldsm4(a[mi], aOff + mi * 1024);
            #pragma unroll
            for (int p = 0; p < 4; p++)
                ldsm4(bb[p], bOff + p * 1024);
            #pragma unroll
            for (int mi = 0; mi < 2; mi++)
                #pragma unroll
                for (int nt = 0; nt < 8; nt++)
                    mma16816(acc[mi][nt], a[mi][0], a[mi][1], a[mi][2], a[mi][3],
                             bb[nt >> 1][(nt & 1) * 2], bb[nt >> 1][(nt & 1) * 2 + 1]);
        }
        s = (s == S_ - 1) ? 0 : s + 1;
        sl = (sl == S_ - 1) ? 0 : sl + 1;
    }
}

// ---------------- K1: QKV GEMM  [32768,512] x [512,1536] ----------------
__global__ __launch_bounds__(256, 2) void qkv_kernel(const float* __restrict__ bq,
                                                     const float* __restrict__ bk,
                                                     const float* __restrict__ bv) {
    extern __shared__ char dyn[];
    const int tid = threadIdx.x, lane = tid & 31, warp = tid >> 5;
    const int g = lane >> 2, tg = lane & 3;
    const int wm = warp >> 1, wn = warp & 1;
    const int mbase = blockIdx.y * 128, nbase = blockIdx.x * 128;

    const __nv_bfloat16* Ag = g_xw + (size_t)mbase * C_;
    const __nv_bfloat16* Bg = g_wT + (size_t)nbase * C_;

    float acc[2][8][4];
    #pragma unroll
    for (int mi = 0; mi < 2; mi++)
        #pragma unroll
        for (int nt = 0; nt < 8; nt++)
            #pragma unroll
            for (int e = 0; e < 4; e++) acc[mi][nt][e] = 0.f;

    gemm_mainloop(smem_u32(dyn), Ag, Bg, acc);

    #pragma unroll
    for (int mi = 0; mi < 2; mi++) {
        int row = mbase + wm * 32 + mi * 16 + g;
        #pragma unroll
        for (int nt = 0; nt < 8; nt++) {
            int col = nbase + wn * 64 + nt * 8 + 2 * tg;
            int sel = col >> 9, ci = col & 511;
            const float* bias = (sel == 0) ? bq : (sel == 1) ? bk : bv;
            float b0f = bias[ci], b1f = bias[ci + 1];
            *reinterpret_cast<uint32_t*>(g_qkv + (size_t)row * N_QKV + col) =
                pack_bf16(acc[mi][nt][0] + b0f, acc[mi][nt][1] + b1f);
            *reinterpret_cast<uint32_t*>(g_qkv + (size_t)(row + 8) * N_QKV + col) =
                pack_bf16(acc[mi][nt][2] + b0f, acc[mi][nt][3] + b1f);
        }
    }
}

// ---------------- K3: output projection + bias + residual (inverse roll scatter) ----------------
__global__ __launch_bounds__(256, 2) void proj_kernel(const float* __restrict__ x,
                                                      const float* __restrict__ bo,
                                                      float* __restrict__ out) {
    extern __shared__ char dyn[];
    const int tid = threadIdx.x, lane = tid & 31, warp = tid >> 5;
    const int g = lane >> 2, tg = lane & 3;
    const int wm = warp >> 1, wn = warp & 1;
    const int mbase = blockIdx.y * 128, nbase = blockIdx.x * 128;

    const __nv_bfloat16* Ag = g_o + (size_t)mbase * C_;
    const __nv_bfloat16* Bg = g_woT + (size_t)nbase * C_;

    float acc[2][8][4];
    #pragma unroll
    for (int mi = 0; mi < 2; mi++)
        #pragma unroll
        for (int nt = 0; nt < 8; nt++)
            #pragma unroll
            for (int e = 0; e < 4; e++) acc[mi][nt][e] = 0.f;

    gemm_mainloop(smem_u32(dyn), Ag, Bg, acc);

    #pragma unroll
    for (int mi = 0; mi < 2; mi++) {
        #pragma unroll
        for (int half = 0; half < 2; half++) {
            int row = mbase + wm * 32 + mi * 16 + g + half * 8;
            int win = row >> 6, t = row & 63;
            int b = win >> 6, wh = (win >> 3) & 7, ww = win & 7;
            int i = t >> 3, j = t & 7;
            int r  = (wh * 8 + i + 4) & 63;
            int cc = (ww * 8 + j + 4) & 63;
            size_t off = (size_t)((b * 64 + r) * 64 + cc) * C_;
            #pragma unroll
            for (int nt = 0; nt < 8; nt++) {
                int col = nbase + wn * 64 + nt * 8 + 2 * tg;
                float2 xr = *reinterpret_cast<const float2*>(x + off + col);
                float2 o;
                o.x = acc[mi][nt][2 * half + 0] + bo[col]     + xr.x;
                o.y = acc[mi][nt][2 * half + 1] + bo[col + 1] + xr.y;
                *reinterpret_cast<float2*>(out + off + col) = o;
            }
        }
    }
}

// ---------------- K2: attention per (window, head) ----------------
__global__ __launch_bounds__(128) void attn_kernel() {
    __shared__ __nv_bfloat16 Qs[64 * 72];
    __shared__ __nv_bfloat16 Ks[64 * 72];
    __shared__ __nv_bfloat16 Vs[64 * 72];

    const int nh = blockIdx.x;
    const int n = nh >> 3, h = nh & 7;
    const int tid = threadIdx.x, lane = tid & 31, warp = tid >> 5;
    const int g = lane >> 2, tg = lane & 3;

    const __nv_bfloat16* src = g_qkv + (size_t)(n * 64) * N_QKV + h * 64;
    const uint32_t qS = smem_u32(Qs), kS = smem_u32(Ks), vS = smem_u32(Vs);
    #pragma unroll
    for (int e = 0; e < 4; e++) {
        int it = tid + e * 128;
        int row = it >> 3, seg = it & 7;
        const __nv_bfloat16* rp = src + (size_t)row * N_QKV + seg * 8;
        cp16(qS + row * 144 + seg * 16, rp);
        cp16(kS + row * 144 + seg * 16, rp + 512);
        cp16(vS + row * 144 + seg * 16, rp + 1024);
    }
    cp_commit();
    cp_wait<0>();
    __syncthreads();

    const uint32_t qB = qS + (warp * 16 + (lane & 15)) * 144 + ((lane >> 4) << 4);
    const uint32_t kB = kS + ((((lane >> 4) & 1) * 8 + (lane & 7)) * 144) + (((lane >> 3) & 1) << 4);
    const uint32_t vB = vS + (((lane & 7) + ((lane >> 3) & 1) * 8) * 144) + (((lane >> 4) & 1) << 4);

    float sc[8][4];
    #pragma unroll
    for (int nt = 0; nt < 8; nt++) { sc[nt][0]=0.f; sc[nt][1]=0.f; sc[nt][2]=0.f; sc[nt][3]=0.f; }
    #pragma unroll
    for (int ks = 0; ks < 4; ks++) {
        uint32_t a[4], bb[4][4];
        ldsm4(a, qB + ks * 32);
        #pragma unroll
        for (int p = 0; p < 4; p++)
            ldsm4(bb[p], kB + (p * 16) * 144 + ks * 32);
        #pragma unroll
        for (int nt = 0; nt < 8; nt++)
            mma16816(sc[nt], a[0], a[1], a[2], a[3],
                     bb[nt >> 1][(nt & 1) * 2], bb[nt >> 1][(nt & 1) * 2 + 1]);
    }

    float mx0 = -1e30f, mx1 = -1e30f;
    #pragma unroll
    for (int nt = 0; nt < 8; nt++) {
        mx0 = fmaxf(mx0, fmaxf(sc[nt][0], sc[nt][1]));
        mx1 = fmaxf(mx1, fmaxf(sc[nt][2], sc[nt][3]));
    }
    mx0 = fmaxf(mx0, __shfl_xor_sync(0xffffffff, mx0, 1));
    mx0 = fmaxf(mx0, __shfl_xor_sync(0xffffffff, mx0, 2));
    mx1 = fmaxf(mx1, __shfl_xor_sync(0xffffffff, mx1, 1));
    mx1 = fmaxf(mx1, __shfl_xor_sync(0xffffffff, mx1, 2));
    float s0 = 0.f, s1 = 0.f;
    #pragma unroll
    for (int nt = 0; nt < 8; nt++) {
        sc[nt][0] = __expf((sc[nt][0] - mx0) * SCALE_);
        sc[nt][1] = __expf((sc[nt][1] - mx0) * SCALE_);
        sc[nt][2] = __expf((sc[nt][2] - mx1) * SCALE_);
        sc[nt][3] = __expf((sc[nt][3] - mx1) * SCALE_);
        s0 += sc[nt][0] + sc[nt][1];
        s1 += sc[nt][2] + sc[nt][3];
    }
    s0 += __shfl_xor_sync(0xffffffff, s0, 1);
    s0 += __shfl_xor_sync(0xffffffff, s0, 2);
    s1 += __shfl_xor_sync(0xffffffff, s1, 1);
    s1 += __shfl_xor_sync(0xffffffff, s1, 2);
    const float i0 = 1.f / s0, i1 = 1.f / s1;

    uint32_t pa[8][2];
    #pragma unroll
    for (int nt = 0; nt < 8; nt++) {
        pa[nt][0] = pack_bf16(sc[nt][0] * i0, sc[nt][1] * i0);
        pa[nt][1] = pack_bf16(sc[nt][2] * i1, sc[nt][3] * i1);
    }

    float oc[8][4];
    #pragma unroll
    for (int nt = 0; nt < 8; nt++) { oc[nt][0]=0.f; oc[nt][1]=0.f; oc[nt][2]=0.f; oc[nt][3]=0.f; }
    #pragma unroll
    for (int ks = 0; ks < 4; ks++) {
        uint32_t bb[4][4];
        #pragma unroll
        for (int p = 0; p < 4; p++)
            ldsm4t(bb[p], vB + (ks * 16) * 144 + p * 32);
        uint32_t a0 = pa[2 * ks][0], a1 = pa[2 * ks][1];
        uint32_t a2 = pa[2 * ks + 1][0], a3 = pa[2 * ks + 1][1];
        #pragma unroll
        for (int nt = 0; nt < 8; nt++)
            mma16816(oc[nt], a0, a1, a2, a3,
                     bb[nt >> 1][(nt & 1) * 2], bb[nt >> 1][(nt & 1) * 2 + 1]);
    }

    const int r0 = warp * 16 + g;
    __nv_bfloat16* dst = g_o + (size_t)(n * 64) * C_ + h * 64;
    #pragma unroll
    for (int nt = 0; nt < 8; nt++) {
        int dcol = nt * 8 + 2 * tg;
        *reinterpret_cast<uint32_t*>(dst + (size_t)r0 * C_ + dcol)       = pack_bf16(oc[nt][0], oc[nt][1]);
        *reinterpret_cast<uint32_t*>(dst + (size_t)(r0 + 8) * C_ + dcol) = pack_bf16(oc[nt][2], oc[nt][3]);
    }
}

// ---------------- launch ----------------
extern "C" void kernel_launch(void* const* d_in, const int* in_sizes, int n_in,
                              void* d_out, int out_size) {
    const float* x  = (const float*)d_in[0];
    const float* wq = (const float*)d_in[1];
    const float* bq = (const float*)d_in[2];
    const float* wk = (const float*)d_in[3];
    const float* bk = (const float*)d_in[4];
    const float* wv = (const float*)d_in[5];
    const float* bv = (const float*)d_in[6];
    const float* wo = (const float*)d_in[7];
    const float* bo = (const float*)d_in[8];
    float* out = (float*)d_out;

    cudaFuncSetAttribute(qkv_kernel,  cudaFuncAttributeMaxDynamicSharedMemorySize, SMEM_DYN);
    cudaFuncSetAttribute(proj_kernel, cudaFuncAttributeMaxDynamicSharedMemorySize, SMEM_DYN);

    prep_kernel<<<17408, 256>>>(x, wq, wk, wv, wo);
    dim3 g1(12, 256);
    qkv_kernel<<<g1, 256, SMEM_DYN>>>(bq, bk, bv);
    attn_kernel<<<NWIN * NH_, 128>>>();
    dim3 g3(4, 256);
    proj_kernel<<<g3, 256, SMEM_DYN>>>(x, bo, out);
}